// round 15
// baseline (speedup 1.0000x reference)
#include <cuda_runtime.h>
#include <cuda_bf16.h>
#include <cstdint>

typedef unsigned long long ull;
typedef uint32_t u32;

#define ROWS_IMG 12996          // 114*114 padded pixels per image
#define GUARD    128
#define TAIL     256
#define TOT_ROWS (GUARD + 32 * ROWS_IMG + TAIL)

// scratch: [row][192 s8] : digit0(64 ci) | digit1(64) | digit2(64)
__device__ __align__(16) signed char g_scratch[(size_t)TOT_ROWS * 192];
__device__ __align__(16) signed char g_wsign[9 * 64 * 64];   // [tap][co][ci] in {-1,0,1}
__device__ float g_wscale[64];                               // pow2 per-co scale

// device-side sync state (zeroed by init kernel each launch)
__device__ int g_cvtready[32];
__device__ int g_padready;
__device__ int g_wready;
__device__ int g_qhead;

// ---------------- helpers ----------------
__device__ __forceinline__ u32 smem_u32(const void* p) {
    u32 a;
    asm("{ .reg .u64 t; cvta.to.shared.u64 t, %1; cvt.u32.u64 %0, t; }" : "=r"(a) : "l"(p));
    return a;
}
__device__ __forceinline__ void cp16(u32 dst, const void* src) {
    asm volatile("cp.async.cg.shared.global [%0], [%1], 16;" :: "r"(dst), "l"(src));
}
#define CP_COMMIT() asm volatile("cp.async.commit_group;" ::: "memory")

__device__ __forceinline__ void ldm4(u32* r, u32 addr) {
    asm volatile("ldmatrix.sync.aligned.m8n8.x4.shared.b16 {%0,%1,%2,%3}, [%4];"
                 : "=r"(r[0]), "=r"(r[1]), "=r"(r[2]), "=r"(r[3]) : "r"(addr));
}
__device__ __forceinline__ void imma16832(int* c, const u32* a, u32 b0, u32 b1) {
    asm volatile(
        "mma.sync.aligned.m16n8k32.row.col.s32.s8.s8.s32 "
        "{%0,%1,%2,%3}, {%4,%5,%6,%7}, {%8,%9}, {%0,%1,%2,%3};"
        : "+r"(c[0]), "+r"(c[1]), "+r"(c[2]), "+r"(c[3])
        : "r"(a[0]), "r"(a[1]), "r"(a[2]), "r"(a[3]), "r"(b0), "r"(b1));
}
__device__ __forceinline__ void nsleep() {
    asm volatile("nanosleep.u32 64;");
}

// ---------------------------------------------------------------------------
// init kernel: zero sync counters (runs before the persistent kernel)
// ---------------------------------------------------------------------------
__global__ void init_sync() {
    if (threadIdx.x < 32) g_cvtready[threadIdx.x] = 0;
    if (threadIdx.x == 32) g_padready = 0;
    if (threadIdx.x == 33) g_wready = 0;
    if (threadIdx.x == 34) g_qhead = 0;
}

// ---------------------------------------------------------------------------
// convert32: 128-thread block converts 32 pixels (q0..q0+31) of image n.
// x = d0*2^-4 + d1*2^-11 + d2*2^-18 + eps, |eps| <= 2^-19 (exact digits)
// ---------------------------------------------------------------------------
__device__ __forceinline__ void convert32(const float* __restrict__ x,
                                          float (*sm)[33], int n, int q0) {
    const int t = threadIdx.x, lane = t & 31, wq = t >> 5;
    #pragma unroll
    for (int r = 0; r < 16; ++r) {
        const int ci = wq * 16 + r;
        sm[ci][lane] = x[((size_t)n * 64 + ci) * 12544 + q0 + lane];
    }
    __syncthreads();
    const int pix = t >> 2, g = t & 3;
    const int q = q0 + pix;
    const int rr = q / 112, cc = q - rr * 112;
    const size_t row = GUARD + (size_t)n * ROWS_IMG + (size_t)(rr + 1) * 114 + cc;
    signed char* dst = g_scratch + row * 192 + g * 16;
    #pragma unroll
    for (int h = 0; h < 2; ++h) {
        union { signed char b[8]; ull u; } p0, p1, p2;
        #pragma unroll
        for (int i = 0; i < 8; ++i) {
            const float f = sm[g * 16 + h * 8 + i][pix];
            float a0 = fminf(127.f, fmaxf(-128.f, rintf(f * 16.f)));
            const float r1 = fmaf(a0, -0.0625f, f);
            float a1 = fminf(127.f, fmaxf(-127.f, rintf(r1 * 2048.f)));
            const float r2 = fmaf(a1, -4.8828125e-4f, r1);
            float a2 = fminf(127.f, fmaxf(-127.f, rintf(r2 * 262144.f)));
            p0.b[i] = (signed char)(int)a0;
            p1.b[i] = (signed char)(int)a1;
            p2.b[i] = (signed char)(int)a2;
        }
        *reinterpret_cast<ull*>(dst + h * 8)       = p0.u;
        *reinterpret_cast<ull*>(dst + 64 + h * 8)  = p1.u;
        *reinterpret_cast<ull*>(dst + 128 + h * 8) = p2.u;
    }
    __syncthreads();
}

// ---------------------------------------------------------------------------
// pad item pb (128 threads): zero border/guard/tail rows
// ---------------------------------------------------------------------------
__device__ __forceinline__ void pad_item(int pb) {
    const int t = threadIdx.x;
    uint4* base = reinterpret_cast<uint4*>(g_scratch);   // 12 uint4 per row
    const uint4 z = make_uint4(0, 0, 0, 0);
    if (pb == 32) {
        for (int i = t; i < GUARD * 12; i += 128) base[i] = z;
        uint4* tail = base + ((size_t)GUARD + 32 * (size_t)ROWS_IMG) * 12;
        for (int i = t; i < TAIL * 12; i += 128) tail[i] = z;
        return;
    }
    const size_t imgrow0 = GUARD + (size_t)pb * ROWS_IMG;
    for (int i = t; i < 228 * 12; i += 128) {
        const int r = i / 12, c = i % 12;
        const size_t row = imgrow0 + (r < 114 ? r : (12882 - 114 + r));
        base[row * 12 + c] = z;
    }
    for (int i = t; i < 112 * 2 * 12; i += 128) {
        const int rp  = 1 + i / 24;
        const int col = 112 + ((i / 12) & 1);
        const int c   = i % 12;
        base[(imgrow0 + (size_t)rp * 114 + col) * 12 + c] = z;
    }
}

// ---------------------------------------------------------------------------
// binarize item co (128 threads, 576 elements)
// ---------------------------------------------------------------------------
__device__ __forceinline__ void binarize_item(int co, const float* __restrict__ w,
                                              float* sred) {
    const int t = threadIdx.x;
    const int lane = t & 31, wq = t >> 5;
    float* rs  = sred;
    float* rsq = sred + 4;
    float* rab = sred + 8;
    float* smv = sred + 12;    // [0]=mean, [1]=scale
    const bool has5 = (t < 64);
    float v[5];
    #pragma unroll
    for (int k = 0; k < 4; ++k) v[k] = w[co * 576 + t + 128 * k];
    v[4] = has5 ? w[co * 576 + t + 512] : 0.f;

    float s = v[0] + v[1] + v[2] + v[3] + v[4];
    #pragma unroll
    for (int o = 16; o > 0; o >>= 1) s += __shfl_down_sync(0xffffffffu, s, o);
    if (lane == 0) rs[wq] = s;
    __syncthreads();
    if (t == 0) smv[0] = (rs[0] + rs[1] + rs[2] + rs[3]) * (1.0f / 576.0f);
    __syncthreads();
    const float mean = smv[0];
    float d[5];
    #pragma unroll
    for (int k = 0; k < 4; ++k) d[k] = v[k] - mean;
    d[4] = has5 ? (v[4] - mean) : 0.f;
    float sq = 0.f, ab = 0.f;
    #pragma unroll
    for (int k = 0; k < 5; ++k) { sq += d[k] * d[k]; ab += fabsf(d[k]); }
    #pragma unroll
    for (int o = 16; o > 0; o >>= 1) {
        sq += __shfl_down_sync(0xffffffffu, sq, o);
        ab += __shfl_down_sync(0xffffffffu, ab, o);
    }
    if (lane == 0) { rsq[wq] = sq; rab[wq] = ab; }
    __syncthreads();
    if (t == 0) {
        const float t2 = rsq[0] + rsq[1] + rsq[2] + rsq[3];
        const float t3 = rab[0] + rab[1] + rab[2] + rab[3];
        const float stdv = sqrtf(t2 / 575.0f);
        const float mean_abs = t3 / (576.0f * stdv);
        smv[1] = exp2f(rintf(log2f(mean_abs)));
    }
    __syncthreads();
    #pragma unroll
    for (int k = 0; k < 4; ++k) {
        const int e = t + 128 * k;
        const signed char sg = (d[k] > 0.f) ? 1 : ((d[k] < 0.f) ? -1 : 0);
        g_wsign[((e % 9) * 64 + co) * 64 + (e / 9)] = sg;
    }
    if (has5) {
        const int e = t + 512;
        const signed char sg = (d[4] > 0.f) ? 1 : ((d[4] < 0.f) ? -1 : 0);
        g_wsign[((e % 9) * 64 + co) * 64 + (e / 9)] = sg;
    }
    if (t == 0) g_wscale[co] = smv[1];
    __syncthreads();
}

// ---------------------------------------------------------------------------
// Persistent fused kernel. Grid = 296 CTAs (2/SM).
//   CTAs 148..295: run 545 pre-pass items (64 binarize, 33 pad, 448 converts)
//                  then join the conv queue.
//   CTAs 0..147  : conv consumers from the start.
// Conv: tile M=128 x N=64, digit-outer s32 shift-merge, scaled LUT, as R14.
// ---------------------------------------------------------------------------
#define AROWS   358                       // 128 + 2*114 + 2
#define APITCH  208
#define A_OFF   0
#define B_OFF   74464                     // 358*208
#define BPITCH  592                       // conflict-free
#define LUT_OFF (B_OFF + 64 * BPITCH)     // 112352
#define WI_OFF  (LUT_OFF + 1792)
#define SMEM_TOTAL (WI_OFF + 96)          // 114240
#define NCTAS   296
#define NWORK   3200
#define PRE_ITEMS 545                     // 64 + 33 + 448
#define CVT_ITEMS_PER_IMG 14              // 28 qblocks each (392/28)

__global__ void __launch_bounds__(128, 2)
fused_persistent(const float* __restrict__ x, const float* __restrict__ w,
                 const float* __restrict__ lut, float* __restrict__ out) {
    extern __shared__ __align__(1024) char smem[];
    const u32 sb = smem_u32(smem);
    const int bid = blockIdx.x;
    const int tid = threadIdx.x, warp = tid >> 5, lane = tid & 31;
    const int wm = warp >> 1;            // 0/1 : 64-px half
    const int wn = warp & 1;             // 0/1 : 32-co half

    // ---------------- producer phase (CTAs 148..295) ----------------
    if (bid >= 148) {
        for (int it = bid - 148; it < PRE_ITEMS; it += 148) {
            if (it < 64) {
                binarize_item(it, w, reinterpret_cast<float*>(smem + WI_OFF + 16));
                __threadfence();
                __syncthreads();
                if (tid == 0) atomicAdd(&g_wready, 1);
            } else if (it < 97) {
                pad_item(it - 64);
                __threadfence();
                __syncthreads();
                if (tid == 0) atomicAdd(&g_padready, 1);
            } else {
                const int ci = it - 97;
                const int n = ci / CVT_ITEMS_PER_IMG;
                const int chunk = ci % CVT_ITEMS_PER_IMG;
                float (*sm)[33] = reinterpret_cast<float (*)[33]>(smem);
                #pragma unroll 1
                for (int k = 0; k < 28; ++k)
                    convert32(x, sm, n, (chunk * 28 + k) * 32);
                __threadfence();
                __syncthreads();
                if (tid == 0) atomicAdd(&g_cvtready[n], 1);
            }
        }
    }

    // ---------------- consumer phase (all CTAs) ----------------
    // wait for weights, then stage B + scaled LUT once
    if (tid == 0) {
        while (atomicAdd(&g_wready, 0) < 64) nsleep();
    }
    __syncthreads();
    __threadfence();
    {
        const char* wsrc = reinterpret_cast<const char*>(g_wsign);
        for (int i = tid; i < 64 * 9 * 4; i += 128) {
            const int tap9 = (i >> 2) % 9, co9 = i / 36, c16 = i & 3;
            cp16(sb + B_OFF + co9 * BPITCH + tap9 * 64 + c16 * 16,
                 wsrc + (size_t)(tap9 * 64 + co9) * 64 + c16 * 16);
        }
    }
    for (int i = tid; i < 448; i += 128) {
        const int co = i / 7;
        reinterpret_cast<float*>(smem + LUT_OFF)[i] =
            lut[i] * (262144.0f / g_wscale[co]);
    }
    CP_COMMIT();                         // group: B

    const int laneR = lane & 15;
    const int blk   = lane >> 4;
    const u32 abase_t0 = sb + A_OFF + (wm * 64 + laneR) * APITCH + blk * 16;
    const u32 bbase_t  = sb + B_OFF + (wn * 32 + laneR) * BPITCH + blk * 16;
    int* s_wi = reinterpret_cast<int*>(smem + WI_OFF);

    while (true) {
        __syncthreads();                 // protect s_wi reuse + smem reuse
        if (tid == 0) *s_wi = atomicAdd(&g_qhead, 1);
        __syncthreads();
        const int wi = *s_wi;
        if (wi >= NWORK) break;
        const int n = wi / 100;
        const int tile = wi % 100;

        // wait for this image's scratch (converts + all pads)
        if (tid == 0) {
            while (atomicAdd(&g_padready, 0) < 33) nsleep();
            while (atomicAdd(&g_cvtready[n], 0) < CVT_ITEMS_PER_IMG) nsleep();
        }
        __syncthreads();
        __threadfence();

        const int s0 = 114 + tile * 128;
        const size_t imgrow0 = GUARD + (size_t)n * ROWS_IMG;
        const char* abase = reinterpret_cast<const char*>(g_scratch) +
                            ((size_t)imgrow0 + (long)s0 - 115) * 192;

        // ---- A stages: 3 digit groups ----
        for (int i = tid; i < AROWS * 4; i += 128) {
            const int r = i >> 2, c = i & 3;
            cp16(sb + A_OFF + r * APITCH + c * 16, abase + (size_t)r * 192 + c * 16);
        }
        CP_COMMIT();                     // group: d0
        for (int i = tid; i < AROWS * 4; i += 128) {
            const int r = i >> 2, c = (i & 3) + 4;
            cp16(sb + A_OFF + r * APITCH + c * 16, abase + (size_t)r * 192 + c * 16);
        }
        CP_COMMIT();                     // group: d1
        for (int i = tid; i < AROWS * 4; i += 128) {
            const int r = i >> 2, c = (i & 3) + 8;
            cp16(sb + A_OFF + r * APITCH + c * 16, abase + (size_t)r * 192 + c * 16);
        }
        CP_COMMIT();                     // group: d2

        // ---- mainloop: digit-outer, one s32 acc set, shift-merge ----
        int sacc[4][4][4];
        #pragma unroll
        for (int mt = 0; mt < 4; ++mt)
            #pragma unroll
            for (int nt = 0; nt < 4; ++nt)
                #pragma unroll
                for (int i = 0; i < 4; ++i) sacc[mt][nt][i] = 0;

        #pragma unroll
        for (int d = 0; d < 3; ++d) {
            if (d == 0)      asm volatile("cp.async.wait_group 2;" ::: "memory");
            else if (d == 1) asm volatile("cp.async.wait_group 1;" ::: "memory");
            else             asm volatile("cp.async.wait_group 0;" ::: "memory");
            __syncthreads();

            #pragma unroll
            for (int s = 0; s < 18; ++s) {
                const int tap = s >> 1, kc = s & 1;
                const int kh = tap / 3, kw = tap - kh * 3;
                u32 af[16], bf[8];
                const u32 ka = abase_t0 + (kh * 114 + kw) * APITCH + d * 64 + kc * 32;
                ldm4(&af[0],  ka);
                ldm4(&af[4],  ka + 16 * APITCH);
                ldm4(&af[8],  ka + 32 * APITCH);
                ldm4(&af[12], ka + 48 * APITCH);
                const u32 bk = bbase_t + tap * 64 + kc * 32;
                ldm4(&bf[0], bk);
                ldm4(&bf[4], bk + 16 * BPITCH);
                #pragma unroll
                for (int mt = 0; mt < 4; ++mt) {
                    imma16832(sacc[mt][0], &af[mt * 4], bf[0], bf[2]);
                    imma16832(sacc[mt][1], &af[mt * 4], bf[1], bf[3]);
                    imma16832(sacc[mt][2], &af[mt * 4], bf[4], bf[6]);
                    imma16832(sacc[mt][3], &af[mt * 4], bf[5], bf[7]);
                }
            }

            if (d < 2) {   // exact merge: next digit is 2^-7 smaller
                #pragma unroll
                for (int mt = 0; mt < 4; ++mt)
                    #pragma unroll
                    for (int nt = 0; nt < 4; ++nt)
                        #pragma unroll
                        for (int i = 0; i < 4; ++i) sacc[mt][nt][i] <<= 7;
            }
        }

        // ---- epilogue: raw (float)acc -> smem [px][65]; bucketize ----
        __syncthreads();
        float* sum = reinterpret_cast<float*>(smem);
        #pragma unroll
        for (int mt = 0; mt < 4; ++mt)
            #pragma unroll
            for (int nt = 0; nt < 4; ++nt)
                #pragma unroll
                for (int i = 0; i < 4; ++i) {
                    const int row = wm * 64 + mt * 16 + (lane >> 2) + ((i >> 1) << 3);
                    const int col = wn * 32 + nt * 8 + ((lane & 3) << 1) + (i & 1);
                    sum[row * 65 + col] = (float)sacc[mt][nt][i];
                }
        __syncthreads();

        const int j = tid;               // pixel 0..127
        const int s = s0 + j;
        const int rimg = s / 114 - 1;
        const int c = s - (rimg + 1) * 114;
        if (c < 112 && rimg < 112) {
            const int q = rimg * 112 + c;
            float* op = out + (size_t)n * 64 * 12544 + q;
            const float* sl = reinterpret_cast<const float*>(smem + LUT_OFF);
            #pragma unroll 4
            for (int co = 0; co < 64; ++co) {
                const float v = sum[j * 65 + co];
                const float* tt = sl + co * 7;
                float r = 0.f;
                if (v >  tt[0]) r = 1.f;
                if (v >= tt[1]) r = 2.f;
                if (v >  tt[2]) r = 3.f;
                if (v >= tt[3]) r = 4.f;
                if (v >  tt[4]) r = 5.f;
                if (v >= tt[5]) r = 6.f;
                if (v >  tt[6]) r = 7.f;
                op[(size_t)co * 12544] = r;
            }
        }
    }
}

// ---------------------------------------------------------------------------
extern "C" void kernel_launch(void* const* d_in, const int* in_sizes, int n_in,
                              void* d_out, int out_size) {
    (void)in_sizes; (void)n_in; (void)out_size;
    const float* x   = (const float*)d_in[0];
    const float* w   = (const float*)d_in[1];
    const float* lut = (const float*)d_in[2];
    float* out = (float*)d_out;

    cudaFuncSetAttribute(fused_persistent,
                         cudaFuncAttributeMaxDynamicSharedMemorySize, SMEM_TOTAL);

    init_sync<<<1, 64>>>();
    fused_persistent<<<NCTAS, 128, SMEM_TOTAL>>>(x, w, lut, out);
}

// round 16
// speedup vs baseline: 1.0495x; 1.0495x over previous
#include <cuda_runtime.h>
#include <cuda_bf16.h>
#include <cstdint>

typedef unsigned long long ull;
typedef uint32_t u32;

#define ROWS_IMG 12996          // 114*114 padded pixels per image
#define GUARD    128
#define TAIL     256
#define TOT_ROWS (GUARD + 32 * ROWS_IMG + TAIL)

// scratch: [row][192 s8] : digit0(64 ci) | digit1(64) | digit2(64)
__device__ __align__(16) signed char g_scratch[(size_t)TOT_ROWS * 192];
__device__ __align__(16) signed char g_wsign[9 * 64 * 64];   // [tap][co][ci] in {-1,0,1}
__device__ float g_wscale[64];                               // pow2 per-co scale

// device-side sync state (zeroed by init kernel each launch)
__device__ int g_cvtready[32];
__device__ int g_padready;
__device__ int g_wready;
__device__ int g_qhead;

// ---------------- helpers ----------------
__device__ __forceinline__ u32 smem_u32(const void* p) {
    u32 a;
    asm("{ .reg .u64 t; cvta.to.shared.u64 t, %1; cvt.u32.u64 %0, t; }" : "=r"(a) : "l"(p));
    return a;
}
__device__ __forceinline__ void cp16(u32 dst, const void* src) {
    asm volatile("cp.async.cg.shared.global [%0], [%1], 16;" :: "r"(dst), "l"(src));
}
#define CP_COMMIT() asm volatile("cp.async.commit_group;" ::: "memory")

__device__ __forceinline__ void ldm4(u32* r, u32 addr) {
    asm volatile("ldmatrix.sync.aligned.m8n8.x4.shared.b16 {%0,%1,%2,%3}, [%4];"
                 : "=r"(r[0]), "=r"(r[1]), "=r"(r[2]), "=r"(r[3]) : "r"(addr));
}
__device__ __forceinline__ void imma16832(int* c, const u32* a, u32 b0, u32 b1) {
    asm volatile(
        "mma.sync.aligned.m16n8k32.row.col.s32.s8.s8.s32 "
        "{%0,%1,%2,%3}, {%4,%5,%6,%7}, {%8,%9}, {%0,%1,%2,%3};"
        : "+r"(c[0]), "+r"(c[1]), "+r"(c[2]), "+r"(c[3])
        : "r"(a[0]), "r"(a[1]), "r"(a[2]), "r"(a[3]), "r"(b0), "r"(b1));
}
__device__ __forceinline__ void nsleep() {
    asm volatile("nanosleep.u32 128;");
}
// acquire load for polling (no RMW traffic)
__device__ __forceinline__ int ldacq(const int* p) {
    int v;
    asm volatile("ld.acquire.gpu.global.s32 %0, [%1];" : "=r"(v) : "l"(p));
    return v;
}

// ---------------------------------------------------------------------------
// init kernel: zero sync counters (runs before the persistent kernel)
// ---------------------------------------------------------------------------
__global__ void init_sync() {
    if (threadIdx.x < 32) g_cvtready[threadIdx.x] = 0;
    if (threadIdx.x == 32) g_padready = 0;
    if (threadIdx.x == 33) g_wready = 0;
    if (threadIdx.x == 34) g_qhead = 0;
}

// ---------------------------------------------------------------------------
// convert32: 128-thread block converts 32 pixels (q0..q0+31) of image n.
// x = d0*2^-4 + d1*2^-11 + d2*2^-18 + eps, |eps| <= 2^-19 (exact digits)
// ---------------------------------------------------------------------------
__device__ __forceinline__ void convert32(const float* __restrict__ x,
                                          float (*sm)[33], int n, int q0) {
    const int t = threadIdx.x, lane = t & 31, wq = t >> 5;
    #pragma unroll
    for (int r = 0; r < 16; ++r) {
        const int ci = wq * 16 + r;
        sm[ci][lane] = x[((size_t)n * 64 + ci) * 12544 + q0 + lane];
    }
    __syncthreads();
    const int pix = t >> 2, g = t & 3;
    const int q = q0 + pix;
    const int rr = q / 112, cc = q - rr * 112;
    const size_t row = GUARD + (size_t)n * ROWS_IMG + (size_t)(rr + 1) * 114 + cc;
    signed char* dst = g_scratch + row * 192 + g * 16;
    union { signed char b[16]; uint4 v; } o0, o1, o2;
    #pragma unroll
    for (int i = 0; i < 16; ++i) {
        const float f = sm[g * 16 + i][pix];
        float a0 = fminf(127.f, fmaxf(-128.f, rintf(f * 16.f)));
        const float r1 = fmaf(a0, -0.0625f, f);
        float a1 = fminf(127.f, fmaxf(-127.f, rintf(r1 * 2048.f)));
        const float r2 = fmaf(a1, -4.8828125e-4f, r1);
        float a2 = fminf(127.f, fmaxf(-127.f, rintf(r2 * 262144.f)));
        o0.b[i] = (signed char)(int)a0;
        o1.b[i] = (signed char)(int)a1;
        o2.b[i] = (signed char)(int)a2;
    }
    *reinterpret_cast<uint4*>(dst)       = o0.v;
    *reinterpret_cast<uint4*>(dst + 64)  = o1.v;
    *reinterpret_cast<uint4*>(dst + 128) = o2.v;
    __syncthreads();
}

// ---------------------------------------------------------------------------
// pad item pb (128 threads): zero border/guard/tail rows
// ---------------------------------------------------------------------------
__device__ __forceinline__ void pad_item(int pb) {
    const int t = threadIdx.x;
    uint4* base = reinterpret_cast<uint4*>(g_scratch);   // 12 uint4 per row
    const uint4 z = make_uint4(0, 0, 0, 0);
    if (pb == 32) {
        for (int i = t; i < GUARD * 12; i += 128) base[i] = z;
        uint4* tail = base + ((size_t)GUARD + 32 * (size_t)ROWS_IMG) * 12;
        for (int i = t; i < TAIL * 12; i += 128) tail[i] = z;
        return;
    }
    const size_t imgrow0 = GUARD + (size_t)pb * ROWS_IMG;
    for (int i = t; i < 228 * 12; i += 128) {
        const int r = i / 12, c = i % 12;
        const size_t row = imgrow0 + (r < 114 ? r : (12882 - 114 + r));
        base[row * 12 + c] = z;
    }
    for (int i = t; i < 112 * 2 * 12; i += 128) {
        const int rp  = 1 + i / 24;
        const int col = 112 + ((i / 12) & 1);
        const int c   = i % 12;
        base[(imgrow0 + (size_t)rp * 114 + col) * 12 + c] = z;
    }
}

// ---------------------------------------------------------------------------
// binarize item co (128 threads, 576 elements)
// ---------------------------------------------------------------------------
__device__ __forceinline__ void binarize_item(int co, const float* __restrict__ w,
                                              float* sred) {
    const int t = threadIdx.x;
    const int lane = t & 31, wq = t >> 5;
    float* rs  = sred;
    float* rsq = sred + 4;
    float* rab = sred + 8;
    float* smv = sred + 12;    // [0]=mean, [1]=scale
    const bool has5 = (t < 64);
    float v[5];
    #pragma unroll
    for (int k = 0; k < 4; ++k) v[k] = w[co * 576 + t + 128 * k];
    v[4] = has5 ? w[co * 576 + t + 512] : 0.f;

    float s = v[0] + v[1] + v[2] + v[3] + v[4];
    #pragma unroll
    for (int o = 16; o > 0; o >>= 1) s += __shfl_down_sync(0xffffffffu, s, o);
    if (lane == 0) rs[wq] = s;
    __syncthreads();
    if (t == 0) smv[0] = (rs[0] + rs[1] + rs[2] + rs[3]) * (1.0f / 576.0f);
    __syncthreads();
    const float mean = smv[0];
    float d[5];
    #pragma unroll
    for (int k = 0; k < 4; ++k) d[k] = v[k] - mean;
    d[4] = has5 ? (v[4] - mean) : 0.f;
    float sq = 0.f, ab = 0.f;
    #pragma unroll
    for (int k = 0; k < 5; ++k) { sq += d[k] * d[k]; ab += fabsf(d[k]); }
    #pragma unroll
    for (int o = 16; o > 0; o >>= 1) {
        sq += __shfl_down_sync(0xffffffffu, sq, o);
        ab += __shfl_down_sync(0xffffffffu, ab, o);
    }
    if (lane == 0) { rsq[wq] = sq; rab[wq] = ab; }
    __syncthreads();
    if (t == 0) {
        const float t2 = rsq[0] + rsq[1] + rsq[2] + rsq[3];
        const float t3 = rab[0] + rab[1] + rab[2] + rab[3];
        const float stdv = sqrtf(t2 / 575.0f);
        const float mean_abs = t3 / (576.0f * stdv);
        smv[1] = exp2f(rintf(log2f(mean_abs)));
    }
    __syncthreads();
    #pragma unroll
    for (int k = 0; k < 4; ++k) {
        const int e = t + 128 * k;
        const signed char sg = (d[k] > 0.f) ? 1 : ((d[k] < 0.f) ? -1 : 0);
        g_wsign[((e % 9) * 64 + co) * 64 + (e / 9)] = sg;
    }
    if (has5) {
        const int e = t + 512;
        const signed char sg = (d[4] > 0.f) ? 1 : ((d[4] < 0.f) ? -1 : 0);
        g_wsign[((e % 9) * 64 + co) * 64 + (e / 9)] = sg;
    }
    if (t == 0) g_wscale[co] = smv[1];
    __syncthreads();
}

// ---------------------------------------------------------------------------
// Persistent fused kernel. Grid = 296 CTAs (2/SM, all co-resident).
// Phase 1 (ALL CTAs): drain 545 prepass items, stride 296 (<=2 items/CTA),
//   image-major publish via threadfence + atomicAdd.
// Phase 2 (per-CTA, immediately after its quota): conv queue consumer with
//   acquire-load spin on per-image readiness.
// Conv body identical to R14: tile M=128 x N=64, digit-outer s32 shift-merge.
// ---------------------------------------------------------------------------
#define AROWS   358                       // 128 + 2*114 + 2
#define APITCH  208
#define A_OFF   0
#define B_OFF   74464                     // 358*208
#define BPITCH  592                       // conflict-free
#define LUT_OFF (B_OFF + 64 * BPITCH)     // 112352
#define WI_OFF  (LUT_OFF + 1792)
#define SMEM_TOTAL (WI_OFF + 96)          // 114240
#define NCTAS   296
#define NWORK   3200
#define PRE_ITEMS 545                     // 64 binarize + 33 pad + 448 cvt
#define CVT_ITEMS_PER_IMG 14              // 28 qblocks each (392/28)

__global__ void __launch_bounds__(128, 2)
fused_persistent(const float* __restrict__ x, const float* __restrict__ w,
                 const float* __restrict__ lut, float* __restrict__ out) {
    extern __shared__ __align__(1024) char smem[];
    const u32 sb = smem_u32(smem);
    const int bid = blockIdx.x;
    const int tid = threadIdx.x, warp = tid >> 5, lane = tid & 31;
    const int wm = warp >> 1;            // 0/1 : 64-px half
    const int wn = warp & 1;             // 0/1 : 32-co half

    // ---------------- phase 1: ALL CTAs produce ----------------
    for (int it = bid; it < PRE_ITEMS; it += NCTAS) {
        if (it < 64) {
            binarize_item(it, w, reinterpret_cast<float*>(smem + WI_OFF + 16));
            __threadfence();
            __syncthreads();
            if (tid == 0) atomicAdd(&g_wready, 1);
        } else if (it < 97) {
            pad_item(it - 64);
            __threadfence();
            __syncthreads();
            if (tid == 0) atomicAdd(&g_padready, 1);
        } else {
            const int ci = it - 97;
            const int n = ci / CVT_ITEMS_PER_IMG;
            const int chunk = ci % CVT_ITEMS_PER_IMG;
            float (*sm)[33] = reinterpret_cast<float (*)[33]>(smem);
            #pragma unroll 1
            for (int k = 0; k < 28; ++k)
                convert32(x, sm, n, (chunk * 28 + k) * 32);
            __threadfence();
            __syncthreads();
            if (tid == 0) atomicAdd(&g_cvtready[n], 1);
        }
    }

    // ---------------- phase 2: consume ----------------
    // wait for weights, then stage B + scaled LUT once
    if (tid == 0) {
        while (ldacq(&g_wready) < 64) nsleep();
    }
    __syncthreads();
    __threadfence();
    {
        const char* wsrc = reinterpret_cast<const char*>(g_wsign);
        for (int i = tid; i < 64 * 9 * 4; i += 128) {
            const int tap9 = (i >> 2) % 9, co9 = i / 36, c16 = i & 3;
            cp16(sb + B_OFF + co9 * BPITCH + tap9 * 64 + c16 * 16,
                 wsrc + (size_t)(tap9 * 64 + co9) * 64 + c16 * 16);
        }
    }
    for (int i = tid; i < 448; i += 128) {
        const int co = i / 7;
        reinterpret_cast<float*>(smem + LUT_OFF)[i] =
            lut[i] * (262144.0f / g_wscale[co]);
    }
    CP_COMMIT();                         // group: B

    const int laneR = lane & 15;
    const int blk   = lane >> 4;
    const u32 abase_t0 = sb + A_OFF + (wm * 64 + laneR) * APITCH + blk * 16;
    const u32 bbase_t  = sb + B_OFF + (wn * 32 + laneR) * BPITCH + blk * 16;
    int* s_wi = reinterpret_cast<int*>(smem + WI_OFF);

    while (true) {
        __syncthreads();                 // protect s_wi reuse + smem reuse
        if (tid == 0) *s_wi = atomicAdd(&g_qhead, 1);
        __syncthreads();
        const int wi = *s_wi;
        if (wi >= NWORK) break;
        const int n = wi / 100;
        const int tile = wi % 100;

        // wait for this image's scratch (converts + all pads) — acquire loads
        if (tid == 0) {
            while (ldacq(&g_padready) < 33) nsleep();
            while (ldacq(&g_cvtready[n]) < CVT_ITEMS_PER_IMG) nsleep();
        }
        __syncthreads();
        __threadfence();

        const int s0 = 114 + tile * 128;
        const size_t imgrow0 = GUARD + (size_t)n * ROWS_IMG;
        const char* abase = reinterpret_cast<const char*>(g_scratch) +
                            ((size_t)imgrow0 + (long)s0 - 115) * 192;

        // ---- A stages: 3 digit groups ----
        for (int i = tid; i < AROWS * 4; i += 128) {
            const int r = i >> 2, c = i & 3;
            cp16(sb + A_OFF + r * APITCH + c * 16, abase + (size_t)r * 192 + c * 16);
        }
        CP_COMMIT();                     // group: d0
        for (int i = tid; i < AROWS * 4; i += 128) {
            const int r = i >> 2, c = (i & 3) + 4;
            cp16(sb + A_OFF + r * APITCH + c * 16, abase + (size_t)r * 192 + c * 16);
        }
        CP_COMMIT();                     // group: d1
        for (int i = tid; i < AROWS * 4; i += 128) {
            const int r = i >> 2, c = (i & 3) + 8;
            cp16(sb + A_OFF + r * APITCH + c * 16, abase + (size_t)r * 192 + c * 16);
        }
        CP_COMMIT();                     // group: d2

        // ---- mainloop: digit-outer, one s32 acc set, shift-merge ----
        int sacc[4][4][4];
        #pragma unroll
        for (int mt = 0; mt < 4; ++mt)
            #pragma unroll
            for (int nt = 0; nt < 4; ++nt)
                #pragma unroll
                for (int i = 0; i < 4; ++i) sacc[mt][nt][i] = 0;

        #pragma unroll
        for (int d = 0; d < 3; ++d) {
            if (d == 0)      asm volatile("cp.async.wait_group 2;" ::: "memory");
            else if (d == 1) asm volatile("cp.async.wait_group 1;" ::: "memory");
            else             asm volatile("cp.async.wait_group 0;" ::: "memory");
            __syncthreads();

            #pragma unroll
            for (int s = 0; s < 18; ++s) {
                const int tap = s >> 1, kc = s & 1;
                const int kh = tap / 3, kw = tap - kh * 3;
                u32 af[16], bf[8];
                const u32 ka = abase_t0 + (kh * 114 + kw) * APITCH + d * 64 + kc * 32;
                ldm4(&af[0],  ka);
                ldm4(&af[4],  ka + 16 * APITCH);
                ldm4(&af[8],  ka + 32 * APITCH);
                ldm4(&af[12], ka + 48 * APITCH);
                const u32 bk = bbase_t + tap * 64 + kc * 32;
                ldm4(&bf[0], bk);
                ldm4(&bf[4], bk + 16 * BPITCH);
                #pragma unroll
                for (int mt = 0; mt < 4; ++mt) {
                    imma16832(sacc[mt][0], &af[mt * 4], bf[0], bf[2]);
                    imma16832(sacc[mt][1], &af[mt * 4], bf[1], bf[3]);
                    imma16832(sacc[mt][2], &af[mt * 4], bf[4], bf[6]);
                    imma16832(sacc[mt][3], &af[mt * 4], bf[5], bf[7]);
                }
            }

            if (d < 2) {   // exact merge: next digit is 2^-7 smaller
                #pragma unroll
                for (int mt = 0; mt < 4; ++mt)
                    #pragma unroll
                    for (int nt = 0; nt < 4; ++nt)
                        #pragma unroll
                        for (int i = 0; i < 4; ++i) sacc[mt][nt][i] <<= 7;
            }
        }

        // ---- epilogue: raw (float)acc -> smem [px][65]; bucketize ----
        __syncthreads();
        float* sum = reinterpret_cast<float*>(smem);
        #pragma unroll
        for (int mt = 0; mt < 4; ++mt)
            #pragma unroll
            for (int nt = 0; nt < 4; ++nt)
                #pragma unroll
                for (int i = 0; i < 4; ++i) {
                    const int row = wm * 64 + mt * 16 + (lane >> 2) + ((i >> 1) << 3);
                    const int col = wn * 32 + nt * 8 + ((lane & 3) << 1) + (i & 1);
                    sum[row * 65 + col] = (float)sacc[mt][nt][i];
                }
        __syncthreads();

        const int j = tid;               // pixel 0..127
        const int s = s0 + j;
        const int rimg = s / 114 - 1;
        const int c = s - (rimg + 1) * 114;
        if (c < 112 && rimg < 112) {
            const int q = rimg * 112 + c;
            float* op = out + (size_t)n * 64 * 12544 + q;
            const float* sl = reinterpret_cast<const float*>(smem + LUT_OFF);
            #pragma unroll 4
            for (int co = 0; co < 64; ++co) {
                const float v = sum[j * 65 + co];
                const float* tt = sl + co * 7;
                float r = 0.f;
                if (v >  tt[0]) r = 1.f;
                if (v >= tt[1]) r = 2.f;
                if (v >  tt[2]) r = 3.f;
                if (v >= tt[3]) r = 4.f;
                if (v >  tt[4]) r = 5.f;
                if (v >= tt[5]) r = 6.f;
                if (v >  tt[6]) r = 7.f;
                op[(size_t)co * 12544] = r;
            }
        }
    }
}

// ---------------------------------------------------------------------------
extern "C" void kernel_launch(void* const* d_in, const int* in_sizes, int n_in,
                              void* d_out, int out_size) {
    (void)in_sizes; (void)n_in; (void)out_size;
    const float* x   = (const float*)d_in[0];
    const float* w   = (const float*)d_in[1];
    const float* lut = (const float*)d_in[2];
    float* out = (float*)d_out;

    cudaFuncSetAttribute(fused_persistent,
                         cudaFuncAttributeMaxDynamicSharedMemorySize, SMEM_TOTAL);

    init_sync<<<1, 64>>>();
    fused_persistent<<<NCTAS, 128, SMEM_TOTAL>>>(x, w, lut, out);
}

// round 17
// speedup vs baseline: 1.2622x; 1.2026x over previous
#include <cuda_runtime.h>
#include <cuda_bf16.h>
#include <cstdint>

typedef unsigned long long ull;
typedef uint32_t u32;

#define ROWS_IMG 12996          // 114*114 padded pixels per image
#define GUARD    128
#define TAIL     256
#define TOT_ROWS (GUARD + 32 * ROWS_IMG + TAIL)

// scratch: [row][192 s8] : digit0(64 ci) | digit1(64) | digit2(64)
__device__ __align__(16) signed char g_scratch[(size_t)TOT_ROWS * 192];
__device__ __align__(16) signed char g_wsign[9 * 64 * 64];   // [tap][co][ci] in {-1,0,1}
__device__ float g_wscale[64];                               // pow2 per-co scale

// ---------------- helpers ----------------
__device__ __forceinline__ u32 smem_u32(const void* p) {
    u32 a;
    asm("{ .reg .u64 t; cvta.to.shared.u64 t, %1; cvt.u32.u64 %0, t; }" : "=r"(a) : "l"(p));
    return a;
}
__device__ __forceinline__ void cp16(u32 dst, const void* src) {
    asm volatile("cp.async.cg.shared.global [%0], [%1], 16;" :: "r"(dst), "l"(src));
}
#define CP_COMMIT() asm volatile("cp.async.commit_group;" ::: "memory")

__device__ __forceinline__ void ldm4(u32* r, u32 addr) {
    asm volatile("ldmatrix.sync.aligned.m8n8.x4.shared.b16 {%0,%1,%2,%3}, [%4];"
                 : "=r"(r[0]), "=r"(r[1]), "=r"(r[2]), "=r"(r[3]) : "r"(addr));
}
__device__ __forceinline__ void imma16832(int* c, const u32* a, u32 b0, u32 b1) {
    asm volatile(
        "mma.sync.aligned.m16n8k32.row.col.s32.s8.s8.s32 "
        "{%0,%1,%2,%3}, {%4,%5,%6,%7}, {%8,%9}, {%0,%1,%2,%3};"
        : "+r"(c[0]), "+r"(c[1]), "+r"(c[2]), "+r"(c[3])
        : "r"(a[0]), "r"(a[1]), "r"(a[2]), "r"(a[3]), "r"(b0), "r"(b1));
}

// ---------------------------------------------------------------------------
// Merged pre-pass kernel, 256 threads/block:
//   blocks [0, 6272)        : convert, 64 pixels/block (x fp32 -> 3x s8 rows)
//   blocks [6272, 6305)     : pad/zero scratch borders + guard + tail
//   blocks [6305, 6369)     : binarize weights -> sign + pow2 scale
// ---------------------------------------------------------------------------
#define CVT_BLKS 6272            // 196 per image * 32 images (64 px each)
#define PAD_BLKS 33
#define PRE_BLKS (CVT_BLKS + PAD_BLKS + 64)

__global__ void __launch_bounds__(256)
prepass_kernel(const float* __restrict__ x, const float* __restrict__ w) {
    const int bid = blockIdx.x;
    const int t = threadIdx.x;

    if (bid < CVT_BLKS) {
        // ---------------- convert: 64 px, 256 threads, uint4 stores ----------
        __shared__ float sm[64][65];
        const int n = bid / 196;
        const int q0 = (bid - n * 196) * 64;
        // stage x: thread t reads 16 ci values for pixel column (t&63)
        {
            const int qc = t & 63, cg = t >> 6;        // cg in 0..3 (16 ci each)
            #pragma unroll
            for (int r = 0; r < 16; ++r) {
                const int ci = cg * 16 + r;
                sm[ci][qc] = x[((size_t)n * 64 + ci) * 12544 + q0 + qc];
            }
        }
        __syncthreads();
        // convert: thread t handles pixel p = t>>2, ci group g = t&3 (16 ci)
        const int p = t >> 2, g = t & 3;
        const int q = q0 + p;
        const int rr = q / 112, cc = q - rr * 112;
        const size_t row = GUARD + (size_t)n * ROWS_IMG + (size_t)(rr + 1) * 114 + cc;
        signed char* dst = g_scratch + row * 192 + g * 16;
        union { signed char b[16]; uint4 v; } o0, o1, o2;
        #pragma unroll
        for (int i = 0; i < 16; ++i) {
            const float f = sm[g * 16 + i][p];
            float a0 = fminf(127.f, fmaxf(-128.f, rintf(f * 16.f)));
            const float r1 = fmaf(a0, -0.0625f, f);
            float a1 = fminf(127.f, fmaxf(-127.f, rintf(r1 * 2048.f)));
            const float r2 = fmaf(a1, -4.8828125e-4f, r1);
            float a2 = fminf(127.f, fmaxf(-127.f, rintf(r2 * 262144.f)));
            o0.b[i] = (signed char)(int)a0;
            o1.b[i] = (signed char)(int)a1;
            o2.b[i] = (signed char)(int)a2;
        }
        *reinterpret_cast<uint4*>(dst)       = o0.v;
        *reinterpret_cast<uint4*>(dst + 64)  = o1.v;
        *reinterpret_cast<uint4*>(dst + 128) = o2.v;
        return;
    }

    if (bid < CVT_BLKS + PAD_BLKS) {
        // ---------------- pad / zero ----------------
        const int pb = bid - CVT_BLKS;
        uint4* base = reinterpret_cast<uint4*>(g_scratch);   // 12 uint4 per row
        const uint4 z = make_uint4(0, 0, 0, 0);
        if (pb == 32) {
            for (int i = t; i < GUARD * 12; i += 256) base[i] = z;
            uint4* tail = base + ((size_t)GUARD + 32 * (size_t)ROWS_IMG) * 12;
            for (int i = t; i < TAIL * 12; i += 256) tail[i] = z;
            return;
        }
        const size_t imgrow0 = GUARD + (size_t)pb * ROWS_IMG;
        for (int i = t; i < 228 * 12; i += 256) {
            const int r = i / 12, c = i % 12;
            const size_t row = imgrow0 + (r < 114 ? r : (12882 - 114 + r));
            base[row * 12 + c] = z;
        }
        for (int i = t; i < 112 * 2 * 12; i += 256) {
            const int rp  = 1 + i / 24;
            const int col = 112 + ((i / 12) & 1);
            const int c   = i % 12;
            base[(imgrow0 + (size_t)rp * 114 + col) * 12 + c] = z;
        }
        return;
    }

    // ---------------- binarize (256 threads, 576 elements) ----------------
    {
        __shared__ float rs[8], rsq[8], rab[8];
        __shared__ float s_mean, s_scale;
        const int co = bid - (CVT_BLKS + PAD_BLKS);
        const int lane = t & 31, wid = t >> 5;
        const bool has3 = (t < 64);
        const float v0 = w[co * 576 + t];
        const float v1 = w[co * 576 + t + 256];
        const float v2 = has3 ? w[co * 576 + t + 512] : 0.f;

        float s = v0 + v1 + v2;
        #pragma unroll
        for (int o = 16; o > 0; o >>= 1) s += __shfl_down_sync(0xffffffffu, s, o);
        if (lane == 0) rs[wid] = s;
        __syncthreads();
        if (t == 0) {
            float tt = 0.f;
            for (int i = 0; i < 8; ++i) tt += rs[i];
            s_mean = tt * (1.0f / 576.0f);
        }
        __syncthreads();
        const float mean = s_mean;
        const float d0 = v0 - mean, d1 = v1 - mean;
        const float d2 = has3 ? (v2 - mean) : 0.f;
        float sq = d0 * d0 + d1 * d1 + d2 * d2;
        float ab = fabsf(d0) + fabsf(d1) + fabsf(d2);
        #pragma unroll
        for (int o = 16; o > 0; o >>= 1) {
            sq += __shfl_down_sync(0xffffffffu, sq, o);
            ab += __shfl_down_sync(0xffffffffu, ab, o);
        }
        if (lane == 0) { rsq[wid] = sq; rab[wid] = ab; }
        __syncthreads();
        if (t == 0) {
            float t2 = 0.f, t3 = 0.f;
            for (int i = 0; i < 8; ++i) { t2 += rsq[i]; t3 += rab[i]; }
            const float stdv = sqrtf(t2 / 575.0f);
            const float mean_abs = t3 / (576.0f * stdv);
            s_scale = exp2f(rintf(log2f(mean_abs)));
        }
        __syncthreads();
        {
            const int e0 = t;
            const signed char sg0 = (d0 > 0.f) ? 1 : ((d0 < 0.f) ? -1 : 0);
            g_wsign[((e0 % 9) * 64 + co) * 64 + (e0 / 9)] = sg0;
            const int e1 = t + 256;
            const signed char sg1 = (d1 > 0.f) ? 1 : ((d1 < 0.f) ? -1 : 0);
            g_wsign[((e1 % 9) * 64 + co) * 64 + (e1 / 9)] = sg1;
            if (has3) {
                const int e2 = t + 512;
                const signed char sg2 = (d2 > 0.f) ? 1 : ((d2 < 0.f) ? -1 : 0);
                g_wsign[((e2 % 9) * 64 + co) * 64 + (e2 / 9)] = sg2;
            }
        }
        if (t == 0) g_wscale[co] = s_scale;
    }
}

// ---------------------------------------------------------------------------
// Main kernel: PERSISTENT implicit-GEMM conv (byte-identical to R14 best).
// Grid = 296 CTAs (2/SM), each loops over (tile, image) work items.
// B tile + scaled LUT staged ONCE per CTA. Per item: 3 digit A-stages via
// cp.async groups, digit-outer s32 shift-merge, max-index bucketize.
// ---------------------------------------------------------------------------
#define AROWS   358                       // 128 + 2*114 + 2
#define APITCH  208
#define A_OFF   0
#define B_OFF   74464                     // 358*208
#define BPITCH  592                       // conflict-free
#define LUT_OFF (B_OFF + 64 * BPITCH)     // 112352
#define SMEM_TOTAL (LUT_OFF + 1792 + 32)  // 114176
#define NCTAS   296
#define NWORK   3200

__global__ void __launch_bounds__(128, 2)
conv_mma_kernel(const float* __restrict__ lut, float* __restrict__ out) {
    extern __shared__ __align__(1024) char smem[];
    const u32 sb = smem_u32(smem);
    const int tid = threadIdx.x, warp = tid >> 5, lane = tid & 31;
    const int wm = warp >> 1;            // 0/1 : 64-px half
    const int wn = warp & 1;             // 0/1 : 32-co half

    // ---- one-time staging: B ([co][tap*64] repack) in its own cp group ----
    {
        const char* wsrc = reinterpret_cast<const char*>(g_wsign);
        for (int i = tid; i < 64 * 9 * 4; i += 128) {
            const int tap9 = (i >> 2) % 9, co9 = i / 36, c16 = i & 3;
            cp16(sb + B_OFF + co9 * BPITCH + tap9 * 64 + c16 * 16,
                 wsrc + (size_t)(tap9 * 64 + co9) * 64 + c16 * 16);
        }
    }
    // one-time scaled LUT: compare raw (float)acc against t * 2^18 / ws
    for (int i = tid; i < 448; i += 128) {
        const int co = i / 7;
        reinterpret_cast<float*>(smem + LUT_OFF)[i] =
            lut[i] * (262144.0f / g_wscale[co]);
    }
    CP_COMMIT();                         // group: B

    const int laneR = lane & 15;
    const int blk   = lane >> 4;
    const u32 abase_t0 = sb + A_OFF + (wm * 64 + laneR) * APITCH + blk * 16;
    const u32 bbase_t  = sb + B_OFF + (wn * 32 + laneR) * BPITCH + blk * 16;

    for (int wi = blockIdx.x; wi < NWORK; wi += NCTAS) {
        const int tile = wi % 100;
        const int n = wi / 100;
        const int s0 = 114 + tile * 128;
        const size_t imgrow0 = GUARD + (size_t)n * ROWS_IMG;
        const char* abase = reinterpret_cast<const char*>(g_scratch) +
                            ((size_t)imgrow0 + (long)s0 - 115) * 192;

        // ---- A stages: 3 digit groups ----
        for (int i = tid; i < AROWS * 4; i += 128) {
            const int r = i >> 2, c = i & 3;
            cp16(sb + A_OFF + r * APITCH + c * 16, abase + (size_t)r * 192 + c * 16);
        }
        CP_COMMIT();                     // group: d0
        for (int i = tid; i < AROWS * 4; i += 128) {
            const int r = i >> 2, c = (i & 3) + 4;
            cp16(sb + A_OFF + r * APITCH + c * 16, abase + (size_t)r * 192 + c * 16);
        }
        CP_COMMIT();                     // group: d1
        for (int i = tid; i < AROWS * 4; i += 128) {
            const int r = i >> 2, c = (i & 3) + 8;
            cp16(sb + A_OFF + r * APITCH + c * 16, abase + (size_t)r * 192 + c * 16);
        }
        CP_COMMIT();                     // group: d2

        // ---- mainloop: digit-outer, one s32 acc set, shift-merge ----
        int sacc[4][4][4];
        #pragma unroll
        for (int mt = 0; mt < 4; ++mt)
            #pragma unroll
            for (int nt = 0; nt < 4; ++nt)
                #pragma unroll
                for (int i = 0; i < 4; ++i) sacc[mt][nt][i] = 0;

        #pragma unroll
        for (int d = 0; d < 3; ++d) {
            if (d == 0)      asm volatile("cp.async.wait_group 2;" ::: "memory");
            else if (d == 1) asm volatile("cp.async.wait_group 1;" ::: "memory");
            else             asm volatile("cp.async.wait_group 0;" ::: "memory");
            __syncthreads();

            #pragma unroll
            for (int s = 0; s < 18; ++s) {
                const int tap = s >> 1, kc = s & 1;
                const int kh = tap / 3, kw = tap - kh * 3;
                u32 af[16], bf[8];
                const u32 ka = abase_t0 + (kh * 114 + kw) * APITCH + d * 64 + kc * 32;
                ldm4(&af[0],  ka);
                ldm4(&af[4],  ka + 16 * APITCH);
                ldm4(&af[8],  ka + 32 * APITCH);
                ldm4(&af[12], ka + 48 * APITCH);
                const u32 bk = bbase_t + tap * 64 + kc * 32;
                ldm4(&bf[0], bk);
                ldm4(&bf[4], bk + 16 * BPITCH);
                #pragma unroll
                for (int mt = 0; mt < 4; ++mt) {
                    imma16832(sacc[mt][0], &af[mt * 4], bf[0], bf[2]);
                    imma16832(sacc[mt][1], &af[mt * 4], bf[1], bf[3]);
                    imma16832(sacc[mt][2], &af[mt * 4], bf[4], bf[6]);
                    imma16832(sacc[mt][3], &af[mt * 4], bf[5], bf[7]);
                }
            }

            if (d < 2) {   // exact merge: next digit is 2^-7 smaller
                #pragma unroll
                for (int mt = 0; mt < 4; ++mt)
                    #pragma unroll
                    for (int nt = 0; nt < 4; ++nt)
                        #pragma unroll
                        for (int i = 0; i < 4; ++i) sacc[mt][nt][i] <<= 7;
            }
        }

        // ---- epilogue: raw (float)acc -> smem [px][65]; bucketize ----
        __syncthreads();
        float* sum = reinterpret_cast<float*>(smem);
        #pragma unroll
        for (int mt = 0; mt < 4; ++mt)
            #pragma unroll
            for (int nt = 0; nt < 4; ++nt)
                #pragma unroll
                for (int i = 0; i < 4; ++i) {
                    const int row = wm * 64 + mt * 16 + (lane >> 2) + ((i >> 1) << 3);
                    const int col = wn * 32 + nt * 8 + ((lane & 3) << 1) + (i & 1);
                    sum[row * 65 + col] = (float)sacc[mt][nt][i];
                }
        __syncthreads();

        const int j = tid;               // pixel 0..127
        const int s = s0 + j;
        const int rimg = s / 114 - 1;
        const int c = s - (rimg + 1) * 114;
        if (c < 112 && rimg < 112) {
            const int q = rimg * 112 + c;
            float* op = out + (size_t)n * 64 * 12544 + q;
            const float* sl = reinterpret_cast<const float*>(smem + LUT_OFF);
            #pragma unroll 4
            for (int co = 0; co < 64; ++co) {
                const float v = sum[j * 65 + co];
                const float* tt = sl + co * 7;
                float r = 0.f;
                if (v >  tt[0]) r = 1.f;
                if (v >= tt[1]) r = 2.f;
                if (v >  tt[2]) r = 3.f;
                if (v >= tt[3]) r = 4.f;
                if (v >  tt[4]) r = 5.f;
                if (v >= tt[5]) r = 6.f;
                if (v >  tt[6]) r = 7.f;
                op[(size_t)co * 12544] = r;
            }
        }
        __syncthreads();   // sum buffer aliases A region: drain before restaging
    }
}

// ---------------------------------------------------------------------------
extern "C" void kernel_launch(void* const* d_in, const int* in_sizes, int n_in,
                              void* d_out, int out_size) {
    (void)in_sizes; (void)n_in; (void)out_size;
    const float* x   = (const float*)d_in[0];
    const float* w   = (const float*)d_in[1];
    const float* lut = (const float*)d_in[2];
    float* out = (float*)d_out;

    cudaFuncSetAttribute(conv_mma_kernel,
                         cudaFuncAttributeMaxDynamicSharedMemorySize, SMEM_TOTAL);

    prepass_kernel<<<PRE_BLKS, 256>>>(x, w);
    conv_mma_kernel<<<NCTAS, 128, SMEM_TOTAL>>>(lut, out);
}